// round 10
// baseline (speedup 1.0000x reference)
#include <cuda_runtime.h>
#include <cuda_fp16.h>
#include <cstdint>
#include <math.h>

// DeformAttn via ldmatrix + mma.sync (m16n8k16 fp16, fp32 accum) — base sm_103 ISA.
// Round 10: NT=512 (16 warps, 4/SMSP) with <=128 regs/thread.
// Warp tile m16(one head) x n32; shared-B co-live K+V (cheap at m16).
// D_TILE=64, two 8-warp groups own d-slices (named barriers, R7 pattern).
// W pre-swizzled fp16 scratch + cp.async staging.

namespace {
constexpr int Bn = 4, Cn = 128, Sn = 9, Dn = 16384;
constexpr int D_TILE = 64;
constexpr int NT = 512;
constexpr float ATT_SCALE = 0.25f;

constexpr int SM_WQ = 0;            // 3 x 32KB swizzled fp16 W
constexpr int SM_WK = 32768;
constexpr int SM_WV = 65536;
constexpr int SM_X  = 98304;        // [buf 0/1][group 0/1] 8KB slices = 32KB
constexpr int SM_TOTAL = 131072;
}

__device__ __align__(16) char g_wh[3 * 32768];

__device__ __forceinline__ uint32_t smem_u32(const void* p) {
    uint32_t a;
    asm("{ .reg .u64 t; cvta.to.shared.u64 t, %1; cvt.u32.u64 %0, t; }" : "=r"(a) : "l"(p));
    return a;
}
// W rows: 256B (128 halfwords), 16B chunks XOR-swizzled by row&7
__device__ __forceinline__ uint32_t swzW(int row, int colh) {
    int chunk = (colh >> 3) ^ (row & 7);
    return (uint32_t)(row * 256 + chunk * 16 + (colh & 7) * 2);
}
// x slice rows: 64B (32 halfwords), 16B chunks XOR-swizzled by (row>>1)&3
__device__ __forceinline__ uint32_t swzX(int row, int colh) {
    int chunk = ((colh >> 3) & 3) ^ ((row >> 1) & 3);
    return (uint32_t)(row * 64 + chunk * 16 + (colh & 7) * 2);
}
__device__ __forceinline__ void ldsm4(uint32_t r[4], uint32_t addr) {
    asm volatile("ldmatrix.sync.aligned.m8n8.x4.shared.b16 {%0,%1,%2,%3}, [%4];"
                 : "=r"(r[0]), "=r"(r[1]), "=r"(r[2]), "=r"(r[3]) : "r"(addr));
}
__device__ __forceinline__ void ldsm4t(uint32_t r[4], uint32_t addr) {
    asm volatile("ldmatrix.sync.aligned.m8n8.x4.trans.shared.b16 {%0,%1,%2,%3}, [%4];"
                 : "=r"(r[0]), "=r"(r[1]), "=r"(r[2]), "=r"(r[3]) : "r"(addr));
}
__device__ __forceinline__ void mma16816(float d[4], const uint32_t a[4], const uint32_t b[2]) {
    asm volatile(
        "mma.sync.aligned.m16n8k16.row.col.f32.f16.f16.f32 "
        "{%0,%1,%2,%3},{%4,%5,%6,%7},{%8,%9},{%0,%1,%2,%3};"
        : "+f"(d[0]), "+f"(d[1]), "+f"(d[2]), "+f"(d[3])
        : "r"(a[0]), "r"(a[1]), "r"(a[2]), "r"(a[3]), "r"(b[0]), "r"(b[1]));
}
__device__ __forceinline__ void grp_bar(int g) {
    asm volatile("bar.sync %0, 256;" :: "r"(g + 1) : "memory");
}

// ---- prep kernel: W fp32 [o][c] -> swizzled fp16 scratch ----
__global__ void prep_w(const float* __restrict__ Wq, const float* __restrict__ Wk,
                       const float* __restrict__ Wv) {
    const int t = blockIdx.x * 256 + threadIdx.x;   // 0..12287
    const int w = t >> 12;
    const int rem = t & 4095;
    const int o = rem >> 5, f4 = rem & 31;
    const float* W = (w == 0) ? Wq : (w == 1) ? Wk : Wv;
    const float4 v = *reinterpret_cast<const float4*>(W + o * 128 + f4 * 4);
    char* dst = g_wh + w * 32768 + swzW(o, f4 * 4);
    *reinterpret_cast<__half2*>(dst)     = __floats2half2_rn(v.x, v.y);
    *reinterpret_cast<__half2*>(dst + 4) = __floats2half2_rn(v.z, v.w);
}

// ---- x slice staging: 256 threads of a group stage [128c x 32d]; 2 waves of pf[2] ----
__device__ __forceinline__ void pf_load2(float4 pf[2], const float* __restrict__ src,
                                         long cstride, int wave, int wt) {
#pragma unroll
    for (int i = 0; i < 2; i++) {
        const int g = wave * 512 + i * 256 + wt;
        const int c = g >> 3, d4 = (g & 7) * 4;
        pf[i] = *reinterpret_cast<const float4*>(src + (long)c * cstride + d4);
    }
}
__device__ __forceinline__ void pf_store2(char* xb, const float4 pf[2], int wave, int wt) {
#pragma unroll
    for (int i = 0; i < 2; i++) {
        const int g = wave * 512 + i * 256 + wt;
        const int c = g >> 3, d4 = (g & 7) * 4;
        const uint32_t off = swzX(c, d4);
        *reinterpret_cast<__half2*>(xb + off)     = __floats2half2_rn(pf[i].x, pf[i].y);
        *reinterpret_cast<__half2*>(xb + off + 4) = __floats2half2_rn(pf[i].z, pf[i].w);
    }
}

__global__ void __launch_bounds__(NT, 1)
deform_attn_hmma(const float* __restrict__ q,  const float* __restrict__ kv,
                 const float* __restrict__ bq, const float* __restrict__ bv,
                 float* __restrict__ out)
{
    extern __shared__ char smem[];
    const uint32_t sb = smem_u32(smem);
    const int tid = threadIdx.x, lane = tid & 31, wid = tid >> 5;
    const int head = wid & 7;           // m16 block (one attention head)
    const int grp  = wid >> 3;          // d-slice group: 0 -> [0,32), 1 -> [32,64)
    const int wt   = tid & 255;         // thread id within group
    const int b = blockIdx.y;
    const int dt = blockIdx.x * D_TILE + grp * 32;

    // A-fragment address (this head's 16 rows)
    const int a_row  = head * 16 + (lane & 7) + ((lane >> 3) & 1) * 8;
    const int a_colq = (lane >> 4) * 8;
    // B-fragment ldsm4t indices
    const int tl = lane >> 3;
    const int b_crem = (tl & 1) * 8 + (lane & 7);
    const int b_drem = (tl >> 1) * 8;

    char* xs0 = smem + SM_X + grp * 8192;
    char* xs1 = smem + SM_X + 16384 + grp * 8192;
    const uint32_t xb0 = sb + SM_X + grp * 8192;
    const uint32_t xb1 = xb0 + 16384;

    // ---- stage all three W via identity cp.async (512 thr x 12 x 16B) ----
#pragma unroll
    for (int i = 0; i < 12; i++) {
        const uint32_t dst = sb + (uint32_t)(tid * 16 + i * 8192);
        const char* src = g_wh + tid * 16 + i * 8192;
        asm volatile("cp.async.cg.shared.global [%0], [%1], 16;" :: "r"(dst), "l"(src));
    }
    asm volatile("cp.async.commit_group;" ::: "memory");

    // ---- stage this group's q slice into buf0 ----
    {
        float4 pf[2];
        pf_load2(pf, q + (long)b * Cn * Dn + dt, (long)Dn, 0, wt);
        pf_store2(xs0, pf, 0, wt);
        pf_load2(pf, q + (long)b * Cn * Dn + dt, (long)Dn, 1, wt);
        pf_store2(xs0, pf, 1, wt);
    }
    asm volatile("cp.async.wait_group 0;" ::: "memory");
    __syncthreads();

    // ---- Q projection: m16 x n32 ----
    float qp[4][4];
#pragma unroll
    for (int n = 0; n < 4; n++) qp[n][0] = qp[n][1] = qp[n][2] = qp[n][3] = 0.0f;
#pragma unroll
    for (int ks = 0; ks < 8; ks++) {
        uint32_t aq[4];
        ldsm4(aq, sb + SM_WQ + swzW(a_row, ks * 16 + a_colq));
        const int c = ks * 16 + b_crem;
        uint32_t r4a[4], r4b[4];
        ldsm4t(r4a, xb0 + swzX(c, b_drem));
        ldsm4t(r4b, xb0 + swzX(c, 16 + b_drem));
        uint32_t f0[2] = {r4a[0], r4a[1]}, f1[2] = {r4a[2], r4a[3]};
        uint32_t f2[2] = {r4b[0], r4b[1]}, f3[2] = {r4b[2], r4b[3]};
        mma16816(qp[0], aq, f0);
        mma16816(qp[1], aq, f1);
        mma16816(qp[2], aq, f2);
        mma16816(qp[3], aq, f3);
    }

    const int r0 = head * 16 + (lane >> 2);
    {
        const float b0 = bq[r0], b1 = bq[r0 + 8];
#pragma unroll
        for (int n = 0; n < 4; n++) {
            qp[n][0] += b0; qp[n][1] += b0; qp[n][2] += b1; qp[n][3] += b1;
        }
    }

    float acc[4][4], den[4][2];
#pragma unroll
    for (int n = 0; n < 4; n++) {
        acc[n][0] = acc[n][1] = acc[n][2] = acc[n][3] = 0.0f;
        den[n][0] = den[n][1] = 0.0f;
    }

    // ---- stage kv sample 0 into buf0 (group-local sync) ----
    grp_bar(grp);
    {
        float4 pf[2];
        pf_load2(pf, kv + (long)(b * Cn) * Sn * Dn + dt, (long)Sn * Dn, 0, wt);
        pf_store2(xs0, pf, 0, wt);
        pf_load2(pf, kv + (long)(b * Cn) * Sn * Dn + dt, (long)Sn * Dn, 1, wt);
        pf_store2(xs0, pf, 1, wt);
    }
    grp_bar(grp);

    for (int s = 0; s < Sn; s++) {
        const uint32_t xb = (s & 1) ? xb1 : xb0;
        char* nxt = ((s + 1) & 1) ? xs1 : xs0;
        const float* nsrc = kv + ((long)(b * Cn) * Sn + (s + 1)) * Dn + dt;

        float4 pf[2];
        if (s + 1 < Sn) pf_load2(pf, nsrc, (long)Sn * Dn, 0, wt);

        // fused K+V, shared B fragments (co-live kp/vp: 16+16 regs at m16)
        float kp[4][4], vp[4][4];
#pragma unroll
        for (int n = 0; n < 4; n++) {
            kp[n][0] = kp[n][1] = kp[n][2] = kp[n][3] = 0.0f;
            vp[n][0] = vp[n][1] = vp[n][2] = vp[n][3] = 0.0f;
        }
#pragma unroll
        for (int ks = 0; ks < 8; ks++) {
            uint32_t ak[4], av[4];
            const uint32_t so = swzW(a_row, ks * 16 + a_colq);
            ldsm4(ak, sb + SM_WK + so);
            ldsm4(av, sb + SM_WV + so);
            const int c = ks * 16 + b_crem;
            uint32_t r4a[4], r4b[4];
            ldsm4t(r4a, xb + swzX(c, b_drem));
            ldsm4t(r4b, xb + swzX(c, 16 + b_drem));
            uint32_t f0[2] = {r4a[0], r4a[1]}, f1[2] = {r4a[2], r4a[3]};
            uint32_t f2[2] = {r4b[0], r4b[1]}, f3[2] = {r4b[2], r4b[3]};
            mma16816(kp[0], ak, f0);
            mma16816(kp[1], ak, f1);
            mma16816(kp[2], ak, f2);
            mma16816(kp[3], ak, f3);
            mma16816(vp[0], av, f0);
            mma16816(vp[1], av, f1);
            mma16816(vp[2], av, f2);
            mma16816(vp[3], av, f3);
        }

        // softmax over this head's 16 channels + weighted V accumulate
#pragma unroll
        for (int n = 0; n < 4; n++) {
            float pe = qp[n][0] * kp[n][0] + qp[n][2] * kp[n][2];
            float po = qp[n][1] * kp[n][1] + qp[n][3] * kp[n][3];
            pe += __shfl_xor_sync(0xffffffffu, pe, 4);
            pe += __shfl_xor_sync(0xffffffffu, pe, 8);
            pe += __shfl_xor_sync(0xffffffffu, pe, 16);
            po += __shfl_xor_sync(0xffffffffu, po, 4);
            po += __shfl_xor_sync(0xffffffffu, po, 8);
            po += __shfl_xor_sync(0xffffffffu, po, 16);
            const float we = __expf(ATT_SCALE * pe);
            const float wo = __expf(ATT_SCALE * po);
            den[n][0] += we; den[n][1] += wo;
            acc[n][0] = fmaf(we, vp[n][0], acc[n][0]);
            acc[n][1] = fmaf(wo, vp[n][1], acc[n][1]);
            acc[n][2] = fmaf(we, vp[n][2], acc[n][2]);
            acc[n][3] = fmaf(wo, vp[n][3], acc[n][3]);
        }

        if (s + 1 < Sn) {
            pf_store2(nxt, pf, 0, wt);
            pf_load2(pf, nsrc, (long)Sn * Dn, 1, wt);
            pf_store2(nxt, pf, 1, wt);
        }
        grp_bar(grp);
    }

    // ---- output: out = acc/den + bv ----
    {
        const float bv0 = bv[r0], bv1 = bv[r0 + 8];
#pragma unroll
        for (int n = 0; n < 4; n++) {
            float* dst = out + ((long)(b * Cn + r0)) * Dn + dt + n * 8 + (lane & 3) * 2;
            const float de = den[n][0], dz = den[n][1];
            float2 v0 = make_float2(acc[n][0] / de + bv0, acc[n][1] / dz + bv0);
            float2 v1 = make_float2(acc[n][2] / de + bv1, acc[n][3] / dz + bv1);
            *reinterpret_cast<float2*>(dst) = v0;
            *reinterpret_cast<float2*>(dst + (long)8 * Dn) = v1;
        }
    }
}

extern "C" void kernel_launch(void* const* d_in, const int* in_sizes, int n_in,
                              void* d_out, int out_size) {
    const float* q  = (const float*)d_in[0];
    const float* kv = (const float*)d_in[1];
    const float* Wq = (const float*)d_in[2];
    const float* bq = (const float*)d_in[3];
    const float* Wk = (const float*)d_in[4];
    // d_in[5] = bk: unused (softmax-invariant)
    const float* Wv = (const float*)d_in[6];
    const float* bv = (const float*)d_in[7];
    float* out = (float*)d_out;

    prep_w<<<48, 256>>>(Wq, Wk, Wv);

    cudaFuncSetAttribute(deform_attn_hmma,
                         cudaFuncAttributeMaxDynamicSharedMemorySize, SM_TOTAL);
    dim3 grid(Dn / D_TILE, Bn);   // 256 x 4 = 1024 blocks
    deform_attn_hmma<<<grid, NT, SM_TOTAL>>>(q, kv, bq, bv, out);
}

// round 11
// speedup vs baseline: 1.1422x; 1.1422x over previous
#include <cuda_runtime.h>
#include <cuda_fp16.h>
#include <cstdint>
#include <math.h>

// DeformAttn via ldmatrix + mma.sync (m16n8k16 fp16, fp32 accum) — base sm_103 ISA.
// Round 11: R7 champion config (D_TILE=64, warp m32 x n32, 8 warps, group barriers,
// prep_w + cp.async W staging) + explicit fragment software-pipelining in proj2:
// bf/akK double-buffered across ks, av issued ahead of the K-MMAs. Staging registers
// halved (two pf[4] waves) to fund the fragment buffers.

namespace {
constexpr int Bn = 4, Cn = 128, Sn = 9, Dn = 16384;
constexpr int D_TILE = 64;
constexpr int NT = 256;
constexpr float ATT_SCALE = 0.25f;

constexpr int SM_WQ = 0;            // 3 x 32KB swizzled fp16 W
constexpr int SM_WK = 32768;
constexpr int SM_WV = 65536;
constexpr int SM_X  = 98304;        // [buf 0/1][group 0/1] 8KB slices = 32KB
constexpr int SM_TOTAL = 131072;
}

__device__ __align__(16) char g_wh[3 * 32768];

__device__ __forceinline__ uint32_t smem_u32(const void* p) {
    uint32_t a;
    asm("{ .reg .u64 t; cvta.to.shared.u64 t, %1; cvt.u32.u64 %0, t; }" : "=r"(a) : "l"(p));
    return a;
}
// W rows: 256B (128 halfwords), 16B chunks XOR-swizzled by row&7
__device__ __forceinline__ uint32_t swzW(int row, int colh) {
    int chunk = (colh >> 3) ^ (row & 7);
    return (uint32_t)(row * 256 + chunk * 16 + (colh & 7) * 2);
}
// x slice rows: 64B (32 halfwords), 16B chunks XOR-swizzled by (row>>1)&3
__device__ __forceinline__ uint32_t swzX(int row, int colh) {
    int chunk = ((colh >> 3) & 3) ^ ((row >> 1) & 3);
    return (uint32_t)(row * 64 + chunk * 16 + (colh & 7) * 2);
}
__device__ __forceinline__ void ldsm4(uint32_t r[4], uint32_t addr) {
    asm volatile("ldmatrix.sync.aligned.m8n8.x4.shared.b16 {%0,%1,%2,%3}, [%4];"
                 : "=r"(r[0]), "=r"(r[1]), "=r"(r[2]), "=r"(r[3]) : "r"(addr));
}
__device__ __forceinline__ void ldsm4t(uint32_t r[4], uint32_t addr) {
    asm volatile("ldmatrix.sync.aligned.m8n8.x4.trans.shared.b16 {%0,%1,%2,%3}, [%4];"
                 : "=r"(r[0]), "=r"(r[1]), "=r"(r[2]), "=r"(r[3]) : "r"(addr));
}
__device__ __forceinline__ void mma16816(float d[4], const uint32_t a[4], const uint32_t b[2]) {
    asm volatile(
        "mma.sync.aligned.m16n8k16.row.col.f32.f16.f16.f32 "
        "{%0,%1,%2,%3},{%4,%5,%6,%7},{%8,%9},{%0,%1,%2,%3};"
        : "+f"(d[0]), "+f"(d[1]), "+f"(d[2]), "+f"(d[3])
        : "r"(a[0]), "r"(a[1]), "r"(a[2]), "r"(a[3]), "r"(b[0]), "r"(b[1]));
}
__device__ __forceinline__ void grp_bar(int g) {
    asm volatile("bar.sync %0, 128;" :: "r"(g + 1) : "memory");
}

// ---- prep kernel: W fp32 [o][c] -> swizzled fp16 scratch ----
__global__ void prep_w(const float* __restrict__ Wq, const float* __restrict__ Wk,
                       const float* __restrict__ Wv) {
    const int t = blockIdx.x * 256 + threadIdx.x;   // 0..12287
    const int w = t >> 12;
    const int rem = t & 4095;
    const int o = rem >> 5, f4 = rem & 31;
    const float* W = (w == 0) ? Wq : (w == 1) ? Wk : Wv;
    const float4 v = *reinterpret_cast<const float4*>(W + o * 128 + f4 * 4);
    char* dst = g_wh + w * 32768 + swzW(o, f4 * 4);
    *reinterpret_cast<__half2*>(dst)     = __floats2half2_rn(v.x, v.y);
    *reinterpret_cast<__half2*>(dst + 4) = __floats2half2_rn(v.z, v.w);
}

// ---- per-group x slice staging in TWO waves: 128 threads, [128c x 32d] fp32->fp16 ----
// wave w covers c-rows [w*64, w*64+64); 4 float4 per thread per wave.
__device__ __forceinline__ void pf_load4(float4 pf[4], const float* __restrict__ src,
                                         long cstride, int wave, int wt) {
#pragma unroll
    for (int i = 0; i < 4; i++) {
        const int g = wave * 512 + i * 128 + wt;
        const int c = g >> 3, d4 = (g & 7) * 4;
        pf[i] = *reinterpret_cast<const float4*>(src + (long)c * cstride + d4);
    }
}
__device__ __forceinline__ void pf_store4(char* xb, const float4 pf[4], int wave, int wt) {
#pragma unroll
    for (int i = 0; i < 4; i++) {
        const int g = wave * 512 + i * 128 + wt;
        const int c = g >> 3, d4 = (g & 7) * 4;
        const uint32_t off = swzX(c, d4);
        *reinterpret_cast<__half2*>(xb + off)     = __floats2half2_rn(pf[i].x, pf[i].y);
        *reinterpret_cast<__half2*>(xb + off + 4) = __floats2half2_rn(pf[i].z, pf[i].w);
    }
}

// ---- Q projection, non-pipelined (runs once) ----
__device__ __forceinline__ void proj1(uint32_t wb, uint32_t xb, int warp_m, int lane,
                                      float acc[2][4][4]) {
#pragma unroll
    for (int t = 0; t < 2; t++)
#pragma unroll
        for (int n = 0; n < 4; n++)
#pragma unroll
            for (int i = 0; i < 4; i++) acc[t][n][i] = 0.0f;
#pragma unroll
    for (int ks = 0; ks < 8; ks++) {
        const int c0 = ks * 16;
        uint32_t a[2][4];
#pragma unroll
        for (int t = 0; t < 2; t++) {
            const int row = warp_m * 32 + t * 16 + (lane & 7) + ((lane >> 3) & 1) * 8;
            const int colh = c0 + (lane >> 4) * 8;
            ldsm4(a[t], wb + swzW(row, colh));
        }
        const int tl = lane >> 3;
        const int c = c0 + (tl & 1) * 8 + (lane & 7);
        const int d = (tl >> 1) * 8;
        uint32_t bf[8];
        ldsm4t(&bf[0], xb + swzX(c, d));
        ldsm4t(&bf[4], xb + swzX(c, 16 + d));
#pragma unroll
        for (int t = 0; t < 2; t++)
#pragma unroll
            for (int n = 0; n < 4; n++) mma16816(acc[t][n], a[t], &bf[n * 2]);
    }
}

// ---- fused K+V projection, fragment-pipelined ----
// bf and akK double-buffered across ks; av(ks) issued before the K-MMAs.
__device__ __forceinline__ void proj2_pipe(
    uint32_t wbK, uint32_t wbV, uint32_t xb,
    int row0, int row1, int a_colq, int b_crem, int b_drem,
    float kp[2][4][4], float vp[2][4][4])
{
#pragma unroll
    for (int t = 0; t < 2; t++)
#pragma unroll
        for (int n = 0; n < 4; n++)
#pragma unroll
            for (int i = 0; i < 4; i++) { kp[t][n][i] = 0.0f; vp[t][n][i] = 0.0f; }

    uint32_t bf[2][8];
    uint32_t akb[2][2][4];
    ldsm4t(&bf[0][0], xb + swzX(b_crem, b_drem));
    ldsm4t(&bf[0][4], xb + swzX(b_crem, 16 + b_drem));
    ldsm4(akb[0][0], wbK + swzW(row0, a_colq));
    ldsm4(akb[0][1], wbK + swzW(row1, a_colq));

#pragma unroll
    for (int ks = 0; ks < 8; ks++) {
        const int cur = ks & 1, nx = cur ^ 1;

        // av for THIS ks — latency covered by the K-MMA burst below
        uint32_t av[2][4];
        ldsm4(av[0], wbV + swzW(row0, ks * 16 + a_colq));
        ldsm4(av[1], wbV + swzW(row1, ks * 16 + a_colq));

        // prefetch bf/akK for NEXT ks — latency covered by K+V MMA bursts
        if (ks < 7) {
            const int c = (ks + 1) * 16 + b_crem;
            ldsm4t(&bf[nx][0], xb + swzX(c, b_drem));
            ldsm4t(&bf[nx][4], xb + swzX(c, 16 + b_drem));
            ldsm4(akb[nx][0], wbK + swzW(row0, (ks + 1) * 16 + a_colq));
            ldsm4(akb[nx][1], wbK + swzW(row1, (ks + 1) * 16 + a_colq));
        }

#pragma unroll
        for (int t = 0; t < 2; t++)
#pragma unroll
            for (int n = 0; n < 4; n++) mma16816(kp[t][n], akb[cur][t], &bf[cur][n * 2]);
#pragma unroll
        for (int t = 0; t < 2; t++)
#pragma unroll
            for (int n = 0; n < 4; n++) mma16816(vp[t][n], av[t], &bf[cur][n * 2]);
    }
}

__global__ void __launch_bounds__(NT, 1)
deform_attn_hmma(const float* __restrict__ q,  const float* __restrict__ kv,
                 const float* __restrict__ bq, const float* __restrict__ bv,
                 float* __restrict__ out)
{
    extern __shared__ char smem[];
    const uint32_t sb = smem_u32(smem);
    const int tid = threadIdx.x, lane = tid & 31, wid = tid >> 5;
    const int warp_m = wid & 3;
    const int grp = wid >> 2;           // warpgroup: 0 -> d [0,32), 1 -> d [32,64)
    const int wt = tid & 127;           // thread id within group
    const int b = blockIdx.y;
    const int dt = blockIdx.x * D_TILE + grp * 32;

    // fragment index precomputation
    const int row0 = warp_m * 32 + (lane & 7) + ((lane >> 3) & 1) * 8;
    const int row1 = row0 + 16;
    const int a_colq = (lane >> 4) * 8;
    const int tl = lane >> 3;
    const int b_crem = (tl & 1) * 8 + (lane & 7);
    const int b_drem = (tl >> 1) * 8;

    // slice buffers: [buf 0/1][group]
    char* xs0 = smem + SM_X + grp * 8192;
    char* xs1 = smem + SM_X + 16384 + grp * 8192;
    const uint32_t xb0 = sb + SM_X + grp * 8192;
    const uint32_t xb1 = xb0 + 16384;

    // ---- stage all three W via identity cp.async from pre-swizzled scratch ----
#pragma unroll
    for (int i = 0; i < 24; i++) {
        const uint32_t dst = sb + (uint32_t)(tid * 16 + i * 4096);
        const char* src = g_wh + tid * 16 + i * 4096;
        asm volatile("cp.async.cg.shared.global [%0], [%1], 16;" :: "r"(dst), "l"(src));
    }
    asm volatile("cp.async.commit_group;" ::: "memory");

    // ---- stage this group's q slice into buf0 ----
    {
        float4 pf[4];
        pf_load4(pf, q + (long)b * Cn * Dn + dt, (long)Dn, 0, wt);
        pf_store4(xs0, pf, 0, wt);
        pf_load4(pf, q + (long)b * Cn * Dn + dt, (long)Dn, 1, wt);
        pf_store4(xs0, pf, 1, wt);
    }
    asm volatile("cp.async.wait_group 0;" ::: "memory");
    __syncthreads();   // W + q slices visible

    // ---- Q projection ----
    float qp[2][4][4];
    proj1(sb + SM_WQ, xb0, warp_m, lane, qp);

    const int r0 = warp_m * 32 + (lane >> 2);
    {
        const float b0 = bq[r0], b1 = bq[r0 + 8], b2 = bq[r0 + 16], b3 = bq[r0 + 24];
#pragma unroll
        for (int n = 0; n < 4; n++) {
            qp[0][n][0] += b0; qp[0][n][1] += b0; qp[0][n][2] += b1; qp[0][n][3] += b1;
            qp[1][n][0] += b2; qp[1][n][1] += b2; qp[1][n][2] += b3; qp[1][n][3] += b3;
        }
    }

    float acc[2][4][4], den[2][4][2];
#pragma unroll
    for (int t = 0; t < 2; t++)
#pragma unroll
        for (int n = 0; n < 4; n++) {
            acc[t][n][0] = acc[t][n][1] = acc[t][n][2] = acc[t][n][3] = 0.0f;
            den[t][n][0] = den[t][n][1] = 0.0f;
        }

    // ---- stage kv sample 0 into buf0 (group-local sync) ----
    grp_bar(grp);
    {
        float4 pf[4];
        pf_load4(pf, kv + (long)(b * Cn) * Sn * Dn + dt, (long)Sn * Dn, 0, wt);
        pf_store4(xs0, pf, 0, wt);
        pf_load4(pf, kv + (long)(b * Cn) * Sn * Dn + dt, (long)Sn * Dn, 1, wt);
        pf_store4(xs0, pf, 1, wt);
    }
    grp_bar(grp);

    float4 pf[4];
    for (int s = 0; s < Sn; s++) {
        const uint32_t xb = (s & 1) ? xb1 : xb0;
        char* nxt = ((s + 1) & 1) ? xs1 : xs0;
        const float* nsrc = kv + ((long)(b * Cn) * Sn + (s + 1)) * Dn + dt;

        if (s + 1 < Sn) pf_load4(pf, nsrc, (long)Sn * Dn, 0, wt);

        float kp[2][4][4], vp[2][4][4];
        proj2_pipe(sb + SM_WK, sb + SM_WV, xb,
                   row0, row1, a_colq, b_crem, b_drem, kp, vp);

        // wave-0 store + wave-1 load; wave-1 LDG latency covered by softmax below
        if (s + 1 < Sn) {
            pf_store4(nxt, pf, 0, wt);
            pf_load4(pf, nsrc, (long)Sn * Dn, 1, wt);
        }

#pragma unroll
        for (int t = 0; t < 2; t++)
#pragma unroll
            for (int n = 0; n < 4; n++) {
                float pe = qp[t][n][0] * kp[t][n][0] + qp[t][n][2] * kp[t][n][2];
                float po = qp[t][n][1] * kp[t][n][1] + qp[t][n][3] * kp[t][n][3];
                pe += __shfl_xor_sync(0xffffffffu, pe, 4);
                pe += __shfl_xor_sync(0xffffffffu, pe, 8);
                pe += __shfl_xor_sync(0xffffffffu, pe, 16);
                po += __shfl_xor_sync(0xffffffffu, po, 4);
                po += __shfl_xor_sync(0xffffffffu, po, 8);
                po += __shfl_xor_sync(0xffffffffu, po, 16);
                const float we = __expf(ATT_SCALE * pe);
                const float wo = __expf(ATT_SCALE * po);
                den[t][n][0] += we; den[t][n][1] += wo;
                acc[t][n][0] = fmaf(we, vp[t][n][0], acc[t][n][0]);
                acc[t][n][1] = fmaf(wo, vp[t][n][1], acc[t][n][1]);
                acc[t][n][2] = fmaf(we, vp[t][n][2], acc[t][n][2]);
                acc[t][n][3] = fmaf(wo, vp[t][n][3], acc[t][n][3]);
            }

        if (s + 1 < Sn) pf_store4(nxt, pf, 1, wt);
        grp_bar(grp);
    }

    // ---- output: out = acc/den + bv ----
    {
        const float bv0 = bv[r0], bv1 = bv[r0 + 8], bv2 = bv[r0 + 16], bv3 = bv[r0 + 24];
        const float bvr[4] = {bv0, bv1, bv2, bv3};
#pragma unroll
        for (int t = 0; t < 2; t++)
#pragma unroll
            for (int n = 0; n < 4; n++) {
                const int row = warp_m * 32 + t * 16 + (lane >> 2);
                float* dst = out + ((long)(b * Cn + row)) * Dn + dt + n * 8 + (lane & 3) * 2;
                const float de = den[t][n][0], dz = den[t][n][1];
                float2 v0 = make_float2(acc[t][n][0] / de + bvr[t * 2],
                                        acc[t][n][1] / dz + bvr[t * 2]);
                float2 v1 = make_float2(acc[t][n][2] / de + bvr[t * 2 + 1],
                                        acc[t][n][3] / dz + bvr[t * 2 + 1]);
                *reinterpret_cast<float2*>(dst) = v0;
                *reinterpret_cast<float2*>(dst + (long)8 * Dn) = v1;
            }
    }
}

extern "C" void kernel_launch(void* const* d_in, const int* in_sizes, int n_in,
                              void* d_out, int out_size) {
    const float* q  = (const float*)d_in[0];
    const float* kv = (const float*)d_in[1];
    const float* Wq = (const float*)d_in[2];
    const float* bq = (const float*)d_in[3];
    const float* Wk = (const float*)d_in[4];
    // d_in[5] = bk: unused (softmax-invariant)
    const float* Wv = (const float*)d_in[6];
    const float* bv = (const float*)d_in[7];
    float* out = (float*)d_out;

    prep_w<<<48, 256>>>(Wq, Wk, Wv);

    cudaFuncSetAttribute(deform_attn_hmma,
                         cudaFuncAttributeMaxDynamicSharedMemorySize, SM_TOTAL);
    dim3 grid(Dn / D_TILE, Bn);   // 256 x 4 = 1024 blocks
    deform_attn_hmma<<<grid, NT, SM_TOTAL>>>(q, kv, bq, bv, out);
}

// round 12
// speedup vs baseline: 1.3154x; 1.1517x over previous
#include <cuda_runtime.h>
#include <cuda_fp16.h>
#include <cstdint>
#include <math.h>

// DeformAttn via ldmatrix + mma.sync (m16n8k16 fp16, fp32 accum) — base sm_103 ISA.
// Round 12: EXACT R7 champion (140us: D_TILE=64, warp m32 x n32, 8 warps, group
// barriers, prep_w + cp.async W staging) + anti-phase k-rotation: odd warps run
// the ks loop starting at ks=4, so the two warps sharing an SMSP sit in opposite
// ldsm/MMA phases and cover each other's LDS latency.

namespace {
constexpr int Bn = 4, Cn = 128, Sn = 9, Dn = 16384;
constexpr int D_TILE = 64;
constexpr int NT = 256;
constexpr float ATT_SCALE = 0.25f;

constexpr int SM_WQ = 0;            // 3 x 32KB swizzled fp16 W
constexpr int SM_WK = 32768;
constexpr int SM_WV = 65536;
constexpr int SM_X  = 98304;        // [buf 0/1][group 0/1] 8KB slices = 32KB
constexpr int SM_TOTAL = 131072;
}

__device__ __align__(16) char g_wh[3 * 32768];

__device__ __forceinline__ uint32_t smem_u32(const void* p) {
    uint32_t a;
    asm("{ .reg .u64 t; cvta.to.shared.u64 t, %1; cvt.u32.u64 %0, t; }" : "=r"(a) : "l"(p));
    return a;
}
// W rows: 256B (128 halfwords), 16B chunks XOR-swizzled by row&7
__device__ __forceinline__ uint32_t swzW(int row, int colh) {
    int chunk = (colh >> 3) ^ (row & 7);
    return (uint32_t)(row * 256 + chunk * 16 + (colh & 7) * 2);
}
// x slice rows: 64B (32 halfwords), 16B chunks XOR-swizzled by (row>>1)&3
__device__ __forceinline__ uint32_t swzX(int row, int colh) {
    int chunk = ((colh >> 3) & 3) ^ ((row >> 1) & 3);
    return (uint32_t)(row * 64 + chunk * 16 + (colh & 7) * 2);
}
__device__ __forceinline__ void ldsm4(uint32_t r[4], uint32_t addr) {
    asm volatile("ldmatrix.sync.aligned.m8n8.x4.shared.b16 {%0,%1,%2,%3}, [%4];"
                 : "=r"(r[0]), "=r"(r[1]), "=r"(r[2]), "=r"(r[3]) : "r"(addr));
}
__device__ __forceinline__ void ldsm4t(uint32_t r[4], uint32_t addr) {
    asm volatile("ldmatrix.sync.aligned.m8n8.x4.trans.shared.b16 {%0,%1,%2,%3}, [%4];"
                 : "=r"(r[0]), "=r"(r[1]), "=r"(r[2]), "=r"(r[3]) : "r"(addr));
}
__device__ __forceinline__ void mma16816(float d[4], const uint32_t a[4], const uint32_t b[2]) {
    asm volatile(
        "mma.sync.aligned.m16n8k16.row.col.f32.f16.f16.f32 "
        "{%0,%1,%2,%3},{%4,%5,%6,%7},{%8,%9},{%0,%1,%2,%3};"
        : "+f"(d[0]), "+f"(d[1]), "+f"(d[2]), "+f"(d[3])
        : "r"(a[0]), "r"(a[1]), "r"(a[2]), "r"(a[3]), "r"(b[0]), "r"(b[1]));
}
__device__ __forceinline__ void grp_bar(int g) {
    asm volatile("bar.sync %0, 128;" :: "r"(g + 1) : "memory");
}

// ---- prep kernel: W fp32 [o][c] -> swizzled fp16 scratch ----
__global__ void prep_w(const float* __restrict__ Wq, const float* __restrict__ Wk,
                       const float* __restrict__ Wv) {
    const int t = blockIdx.x * 256 + threadIdx.x;   // 0..12287
    const int w = t >> 12;
    const int rem = t & 4095;
    const int o = rem >> 5, f4 = rem & 31;
    const float* W = (w == 0) ? Wq : (w == 1) ? Wk : Wv;
    const float4 v = *reinterpret_cast<const float4*>(W + o * 128 + f4 * 4);
    char* dst = g_wh + w * 32768 + swzW(o, f4 * 4);
    *reinterpret_cast<__half2*>(dst)     = __floats2half2_rn(v.x, v.y);
    *reinterpret_cast<__half2*>(dst + 4) = __floats2half2_rn(v.z, v.w);
}

// ---- per-group x slice staging: 128 threads stage [128c x 32d] fp32 -> fp16 ----
__device__ __forceinline__ void pf_load(float4 pf[8], const float* __restrict__ src,
                                        long cstride, int wt) {
#pragma unroll
    for (int i = 0; i < 8; i++) {
        const int g = i * 128 + wt;
        const int c = g >> 3, d4 = (g & 7) * 4;
        pf[i] = *reinterpret_cast<const float4*>(src + (long)c * cstride + d4);
    }
}
__device__ __forceinline__ void pf_store(char* xb, const float4 pf[8], int wt) {
#pragma unroll
    for (int i = 0; i < 8; i++) {
        const int g = i * 128 + wt;
        const int c = g >> 3, d4 = (g & 7) * 4;
        const uint32_t off = swzX(c, d4);
        *reinterpret_cast<__half2*>(xb + off)     = __floats2half2_rn(pf[i].x, pf[i].y);
        *reinterpret_cast<__half2*>(xb + off + 4) = __floats2half2_rn(pf[i].z, pf[i].w);
    }
}

// fused K+V projection, warp tile m32 x n32; ks order rotated by `phase`
__device__ __forceinline__ void proj2(uint32_t wbK, uint32_t wbV, uint32_t xb,
                                      int warp_m, int lane, int phase,
                                      float kp[2][4][4], float vp[2][4][4]) {
#pragma unroll
    for (int t = 0; t < 2; t++)
#pragma unroll
        for (int n = 0; n < 4; n++)
#pragma unroll
            for (int i = 0; i < 4; i++) { kp[t][n][i] = 0.0f; vp[t][n][i] = 0.0f; }
#pragma unroll
    for (int ks = 0; ks < 8; ks++) {
        const int kk = (ks + phase) & 7;     // anti-phase rotation across warps
        const int c0 = kk * 16;
        uint32_t ak[2][4], av[2][4];
#pragma unroll
        for (int t = 0; t < 2; t++) {
            const int row = warp_m * 32 + t * 16 + (lane & 7) + ((lane >> 3) & 1) * 8;
            const int colh = c0 + (lane >> 4) * 8;
            const uint32_t so = swzW(row, colh);
            ldsm4(ak[t], wbK + so);
            ldsm4(av[t], wbV + so);
        }
        const int tl = lane >> 3;
        const int c = c0 + (tl & 1) * 8 + (lane & 7);
        const int d = (tl >> 1) * 8;
        uint32_t bf[4][2];
#pragma unroll
        for (int np = 0; np < 2; np++) {
            uint32_t r4[4];
            ldsm4t(r4, xb + swzX(c, np * 16 + d));
            bf[np * 2][0] = r4[0]; bf[np * 2][1] = r4[1];
            bf[np * 2 + 1][0] = r4[2]; bf[np * 2 + 1][1] = r4[3];
        }
#pragma unroll
        for (int t = 0; t < 2; t++)
#pragma unroll
            for (int n = 0; n < 4; n++) {
                mma16816(kp[t][n], ak[t], bf[n]);
                mma16816(vp[t][n], av[t], bf[n]);
            }
    }
}
// single projection (Q only), also phase-rotated
__device__ __forceinline__ void proj1(uint32_t wb, uint32_t xb, int warp_m, int lane,
                                      int phase, float acc[2][4][4]) {
#pragma unroll
    for (int t = 0; t < 2; t++)
#pragma unroll
        for (int n = 0; n < 4; n++)
#pragma unroll
            for (int i = 0; i < 4; i++) acc[t][n][i] = 0.0f;
#pragma unroll
    for (int ks = 0; ks < 8; ks++) {
        const int kk = (ks + phase) & 7;
        const int c0 = kk * 16;
        uint32_t a[2][4];
#pragma unroll
        for (int t = 0; t < 2; t++) {
            const int row = warp_m * 32 + t * 16 + (lane & 7) + ((lane >> 3) & 1) * 8;
            const int colh = c0 + (lane >> 4) * 8;
            ldsm4(a[t], wb + swzW(row, colh));
        }
        const int tl = lane >> 3;
        const int c = c0 + (tl & 1) * 8 + (lane & 7);
        const int d = (tl >> 1) * 8;
        uint32_t bf[4][2];
#pragma unroll
        for (int np = 0; np < 2; np++) {
            uint32_t r4[4];
            ldsm4t(r4, xb + swzX(c, np * 16 + d));
            bf[np * 2][0] = r4[0]; bf[np * 2][1] = r4[1];
            bf[np * 2 + 1][0] = r4[2]; bf[np * 2 + 1][1] = r4[3];
        }
#pragma unroll
        for (int t = 0; t < 2; t++)
#pragma unroll
            for (int n = 0; n < 4; n++) mma16816(acc[t][n], a[t], bf[n]);
    }
}

__global__ void __launch_bounds__(NT, 1)
deform_attn_hmma(const float* __restrict__ q,  const float* __restrict__ kv,
                 const float* __restrict__ bq, const float* __restrict__ bv,
                 float* __restrict__ out)
{
    extern __shared__ char smem[];
    const uint32_t sb = smem_u32(smem);
    const int tid = threadIdx.x, lane = tid & 31, wid = tid >> 5;
    const int warp_m = wid & 3;
    const int grp = wid >> 2;           // warpgroup: 0 -> d [0,32), 1 -> d [32,64)
    const int wt = tid & 127;           // thread id within group
    const int phase = (wid & 1) * 4;    // SMSP partner warps get opposite k-phase
    const int b = blockIdx.y;
    const int dt = blockIdx.x * D_TILE + grp * 32;

    // slice buffers: [buf 0/1][group]
    char* xs0 = smem + SM_X + grp * 8192;
    char* xs1 = smem + SM_X + 16384 + grp * 8192;
    const uint32_t xb0 = sb + SM_X + grp * 8192;
    const uint32_t xb1 = xb0 + 16384;

    // ---- stage all three W via identity cp.async from pre-swizzled scratch ----
#pragma unroll
    for (int i = 0; i < 24; i++) {
        const uint32_t dst = sb + (uint32_t)(tid * 16 + i * 4096);
        const char* src = g_wh + tid * 16 + i * 4096;
        asm volatile("cp.async.cg.shared.global [%0], [%1], 16;" :: "r"(dst), "l"(src));
    }
    asm volatile("cp.async.commit_group;" ::: "memory");

    // ---- stage this group's q slice into buf0 ----
    {
        float4 pf[8];
        pf_load(pf, q + (long)b * Cn * Dn + dt, (long)Dn, wt);
        pf_store(xs0, pf, wt);
    }
    asm volatile("cp.async.wait_group 0;" ::: "memory");
    __syncthreads();   // W + q slices visible to everyone

    // ---- Q projection (warp m32 x group-slice n32) ----
    float qp[2][4][4];
    proj1(sb + SM_WQ, xb0, warp_m, lane, phase, qp);

    const int r0 = warp_m * 32 + (lane >> 2);
    {
        const float b0 = bq[r0], b1 = bq[r0 + 8], b2 = bq[r0 + 16], b3 = bq[r0 + 24];
#pragma unroll
        for (int n = 0; n < 4; n++) {
            qp[0][n][0] += b0; qp[0][n][1] += b0; qp[0][n][2] += b1; qp[0][n][3] += b1;
            qp[1][n][0] += b2; qp[1][n][1] += b2; qp[1][n][2] += b3; qp[1][n][3] += b3;
        }
    }

    float acc[2][4][4], den[2][4][2];
#pragma unroll
    for (int t = 0; t < 2; t++)
#pragma unroll
        for (int n = 0; n < 4; n++) {
            acc[t][n][0] = acc[t][n][1] = acc[t][n][2] = acc[t][n][3] = 0.0f;
            den[t][n][0] = den[t][n][1] = 0.0f;
        }

    // ---- stage kv sample 0 into buf0 (group-local sync only) ----
    grp_bar(grp);   // group's Q-proj readers done with buf0
    {
        float4 pf[8];
        pf_load(pf, kv + (long)(b * Cn) * Sn * Dn + dt, (long)Sn * Dn, wt);
        pf_store(xs0, pf, wt);
    }
    grp_bar(grp);

    float4 pf[8];
    for (int s = 0; s < Sn; s++) {
        const uint32_t xb = (s & 1) ? xb1 : xb0;
        char* nxt = ((s + 1) & 1) ? xs1 : xs0;

        if (s + 1 < Sn)
            pf_load(pf, kv + ((long)(b * Cn) * Sn + (s + 1)) * Dn + dt, (long)Sn * Dn, wt);

        float kp[2][4][4], vp[2][4][4];
        proj2(sb + SM_WK, sb + SM_WV, xb, warp_m, lane, phase, kp, vp);

#pragma unroll
        for (int t = 0; t < 2; t++)
#pragma unroll
            for (int n = 0; n < 4; n++) {
                float pe = qp[t][n][0] * kp[t][n][0] + qp[t][n][2] * kp[t][n][2];
                float po = qp[t][n][1] * kp[t][n][1] + qp[t][n][3] * kp[t][n][3];
                pe += __shfl_xor_sync(0xffffffffu, pe, 4);
                pe += __shfl_xor_sync(0xffffffffu, pe, 8);
                pe += __shfl_xor_sync(0xffffffffu, pe, 16);
                po += __shfl_xor_sync(0xffffffffu, po, 4);
                po += __shfl_xor_sync(0xffffffffu, po, 8);
                po += __shfl_xor_sync(0xffffffffu, po, 16);
                const float we = __expf(ATT_SCALE * pe);
                const float wo = __expf(ATT_SCALE * po);
                den[t][n][0] += we; den[t][n][1] += wo;
                acc[t][n][0] = fmaf(we, vp[t][n][0], acc[t][n][0]);
                acc[t][n][1] = fmaf(wo, vp[t][n][1], acc[t][n][1]);
                acc[t][n][2] = fmaf(we, vp[t][n][2], acc[t][n][2]);
                acc[t][n][3] = fmaf(wo, vp[t][n][3], acc[t][n][3]);
            }

        // write s+1 into the buffer whose readers finished before the LAST group barrier
        if (s + 1 < Sn) pf_store(nxt, pf, wt);
        grp_bar(grp);
    }

    // ---- output: out = acc/den + bv ----
    {
        const float bv0 = bv[r0], bv1 = bv[r0 + 8], bv2 = bv[r0 + 16], bv3 = bv[r0 + 24];
        const float bvr[4] = {bv0, bv1, bv2, bv3};
#pragma unroll
        for (int t = 0; t < 2; t++)
#pragma unroll
            for (int n = 0; n < 4; n++) {
                const int row = warp_m * 32 + t * 16 + (lane >> 2);
                float* dst = out + ((long)(b * Cn + row)) * Dn + dt + n * 8 + (lane & 3) * 2;
                const float de = den[t][n][0], dz = den[t][n][1];
                float2 v0 = make_float2(acc[t][n][0] / de + bvr[t * 2],
                                        acc[t][n][1] / dz + bvr[t * 2]);
                float2 v1 = make_float2(acc[t][n][2] / de + bvr[t * 2 + 1],
                                        acc[t][n][3] / dz + bvr[t * 2 + 1]);
                *reinterpret_cast<float2*>(dst) = v0;
                *reinterpret_cast<float2*>(dst + (long)8 * Dn) = v1;
            }
    }
}

extern "C" void kernel_launch(void* const* d_in, const int* in_sizes, int n_in,
                              void* d_out, int out_size) {
    const float* q  = (const float*)d_in[0];
    const float* kv = (const float*)d_in[1];
    const float* Wq = (const float*)d_in[2];
    const float* bq = (const float*)d_in[3];
    const float* Wk = (const float*)d_in[4];
    // d_in[5] = bk: unused (softmax-invariant)
    const float* Wv = (const float*)d_in[6];
    const float* bv = (const float*)d_in[7];
    float* out = (float*)d_out;

    prep_w<<<48, 256>>>(Wq, Wk, Wv);

    cudaFuncSetAttribute(deform_attn_hmma,
                         cudaFuncAttributeMaxDynamicSharedMemorySize, SM_TOTAL);
    dim3 grid(Dn / D_TILE, Bn);   // 256 x 4 = 1024 blocks
    deform_attn_hmma<<<grid, NT, SM_TOTAL>>>(q, kv, bq, bv, out);
}

// round 13
// speedup vs baseline: 1.3826x; 1.0511x over previous
#include <cuda_runtime.h>
#include <cuda_fp16.h>
#include <cstdint>
#include <math.h>

// DeformAttn via ldmatrix + mma.sync (m16n8k16 fp16, fp32 accum) — base sm_103 ISA.
// Round 13: R7 champion body (D_TILE=64, warp m32 x n32, 8 warps, group barriers) +
//  (a) ks-major affine W layout: A-fragment ldsm addresses are base + ks*4096
//      (immediate-foldable, conflict-free) — removes per-ks swizzle ALU.
//  (b) persistent CTAs (grid=152): W staged + synced ONCE per CTA, ~7 tiles each;
//      bq/bv hoisted out of the tile loop.

namespace {
constexpr int Bn = 4, Cn = 128, Sn = 9, Dn = 16384;
constexpr int D_TILE = 64;
constexpr int NT = 256;
constexpr int N_TILES = (Dn / D_TILE) * Bn;   // 1024
constexpr int GRID_X = 152;                   // GB300 SM count
constexpr float ATT_SCALE = 0.25f;

constexpr int SM_WQ = 0;            // 3 x 32KB ks-major fp16 W
constexpr int SM_WK = 32768;
constexpr int SM_WV = 65536;
constexpr int SM_X  = 98304;        // [buf 0/1][group 0/1] 8KB slices = 32KB
constexpr int SM_TOTAL = 131072;
}

__device__ __align__(16) char g_wh[3 * 32768];

__device__ __forceinline__ uint32_t smem_u32(const void* p) {
    uint32_t a;
    asm("{ .reg .u64 t; cvta.to.shared.u64 t, %1; cvt.u32.u64 %0, t; }" : "=r"(a) : "l"(p));
    return a;
}
// x slice rows: 64B (32 halfwords), 16B chunks XOR-swizzled by (row>>1)&3 (ks-affine)
__device__ __forceinline__ uint32_t swzX(int row, int colh) {
    int chunk = ((colh >> 3) & 3) ^ ((row >> 1) & 3);
    return (uint32_t)(row * 64 + chunk * 16 + (colh & 7) * 2);
}
__device__ __forceinline__ void ldsm4(uint32_t r[4], uint32_t addr) {
    asm volatile("ldmatrix.sync.aligned.m8n8.x4.shared.b16 {%0,%1,%2,%3}, [%4];"
                 : "=r"(r[0]), "=r"(r[1]), "=r"(r[2]), "=r"(r[3]) : "r"(addr));
}
__device__ __forceinline__ void ldsm4t(uint32_t r[4], uint32_t addr) {
    asm volatile("ldmatrix.sync.aligned.m8n8.x4.trans.shared.b16 {%0,%1,%2,%3}, [%4];"
                 : "=r"(r[0]), "=r"(r[1]), "=r"(r[2]), "=r"(r[3]) : "r"(addr));
}
__device__ __forceinline__ void mma16816(float d[4], const uint32_t a[4], const uint32_t b[2]) {
    asm volatile(
        "mma.sync.aligned.m16n8k16.row.col.f32.f16.f16.f32 "
        "{%0,%1,%2,%3},{%4,%5,%6,%7},{%8,%9},{%0,%1,%2,%3};"
        : "+f"(d[0]), "+f"(d[1]), "+f"(d[2]), "+f"(d[3])
        : "r"(a[0]), "r"(a[1]), "r"(a[2]), "r"(a[3]), "r"(b[0]), "r"(b[1]));
}
__device__ __forceinline__ void grp_bar(int g) {
    asm volatile("bar.sync %0, 128;" :: "r"(g + 1) : "memory");
}

// ---- prep kernel: W fp32 [o][c] -> ks-major conflict-free fp16 scratch ----
// addr = ks*4096 + o*32 + ((half ^ ((o>>2)&1)) << 4) + pos*2
__global__ void prep_w(const float* __restrict__ Wq, const float* __restrict__ Wk,
                       const float* __restrict__ Wv) {
    const int t = blockIdx.x * 256 + threadIdx.x;   // 0..12287
    const int w = t >> 12;
    const int rem = t & 4095;
    const int o = rem >> 5, f4 = rem & 31;
    const float* W = (w == 0) ? Wq : (w == 1) ? Wk : Wv;
    const float4 v = *reinterpret_cast<const float4*>(W + o * 128 + f4 * 4);
    const int ks = f4 >> 2;
    const int half = (f4 >> 1) & 1;
    const int pos = (f4 & 1) * 4;
    char* dst = g_wh + w * 32768 + ks * 4096 + o * 32
              + ((half ^ ((o >> 2) & 1)) << 4) + pos * 2;
    *reinterpret_cast<__half2*>(dst)     = __floats2half2_rn(v.x, v.y);
    *reinterpret_cast<__half2*>(dst + 4) = __floats2half2_rn(v.z, v.w);
}

// ---- per-group x slice staging: 128 threads stage [128c x 32d] fp32 -> fp16 ----
__device__ __forceinline__ void pf_load(float4 pf[8], const float* __restrict__ src,
                                        long cstride, int wt) {
#pragma unroll
    for (int i = 0; i < 8; i++) {
        const int g = i * 128 + wt;
        const int c = g >> 3, d4 = (g & 7) * 4;
        pf[i] = *reinterpret_cast<const float4*>(src + (long)c * cstride + d4);
    }
}
__device__ __forceinline__ void pf_store(char* xb, const float4 pf[8], int wt) {
#pragma unroll
    for (int i = 0; i < 8; i++) {
        const int g = i * 128 + wt;
        const int c = g >> 3, d4 = (g & 7) * 4;
        const uint32_t off = swzX(c, d4);
        *reinterpret_cast<__half2*>(xb + off)     = __floats2half2_rn(pf[i].x, pf[i].y);
        *reinterpret_cast<__half2*>(xb + off + 4) = __floats2half2_rn(pf[i].z, pf[i].w);
    }
}

// fused K+V projection, warp tile m32 x n32, affine A addresses
__device__ __forceinline__ void proj2(uint32_t wbK, uint32_t wbV, uint32_t xb,
                                      uint32_t aw0, uint32_t aw1,
                                      int b_crem, int b_drem,
                                      float kp[2][4][4], float vp[2][4][4]) {
#pragma unroll
    for (int t = 0; t < 2; t++)
#pragma unroll
        for (int n = 0; n < 4; n++)
#pragma unroll
            for (int i = 0; i < 4; i++) { kp[t][n][i] = 0.0f; vp[t][n][i] = 0.0f; }
#pragma unroll
    for (int ks = 0; ks < 8; ks++) {
        uint32_t ak[2][4], av[2][4];
        ldsm4(ak[0], wbK + ks * 4096 + aw0);
        ldsm4(ak[1], wbK + ks * 4096 + aw1);
        ldsm4(av[0], wbV + ks * 4096 + aw0);
        ldsm4(av[1], wbV + ks * 4096 + aw1);
        const int c = ks * 16 + b_crem;
        uint32_t bf[4][2];
#pragma unroll
        for (int np = 0; np < 2; np++) {
            uint32_t r4[4];
            ldsm4t(r4, xb + swzX(c, np * 16 + b_drem));
            bf[np * 2][0] = r4[0]; bf[np * 2][1] = r4[1];
            bf[np * 2 + 1][0] = r4[2]; bf[np * 2 + 1][1] = r4[3];
        }
#pragma unroll
        for (int t = 0; t < 2; t++)
#pragma unroll
            for (int n = 0; n < 4; n++) {
                mma16816(kp[t][n], ak[t], bf[n]);
                mma16816(vp[t][n], av[t], bf[n]);
            }
    }
}
// single projection (Q only), affine A addresses
__device__ __forceinline__ void proj1(uint32_t wb, uint32_t xb,
                                      uint32_t aw0, uint32_t aw1,
                                      int b_crem, int b_drem, float acc[2][4][4]) {
#pragma unroll
    for (int t = 0; t < 2; t++)
#pragma unroll
        for (int n = 0; n < 4; n++)
#pragma unroll
            for (int i = 0; i < 4; i++) acc[t][n][i] = 0.0f;
#pragma unroll
    for (int ks = 0; ks < 8; ks++) {
        uint32_t a[2][4];
        ldsm4(a[0], wb + ks * 4096 + aw0);
        ldsm4(a[1], wb + ks * 4096 + aw1);
        const int c = ks * 16 + b_crem;
        uint32_t bf[4][2];
#pragma unroll
        for (int np = 0; np < 2; np++) {
            uint32_t r4[4];
            ldsm4t(r4, xb + swzX(c, np * 16 + b_drem));
            bf[np * 2][0] = r4[0]; bf[np * 2][1] = r4[1];
            bf[np * 2 + 1][0] = r4[2]; bf[np * 2 + 1][1] = r4[3];
        }
#pragma unroll
        for (int t = 0; t < 2; t++)
#pragma unroll
            for (int n = 0; n < 4; n++) mma16816(acc[t][n], a[t], bf[n]);
    }
}

__global__ void __launch_bounds__(NT, 1)
deform_attn_hmma(const float* __restrict__ q,  const float* __restrict__ kv,
                 const float* __restrict__ bq, const float* __restrict__ bv,
                 float* __restrict__ out)
{
    extern __shared__ char smem[];
    const uint32_t sb = smem_u32(smem);
    const int tid = threadIdx.x, lane = tid & 31, wid = tid >> 5;
    const int warp_m = wid & 3;
    const int grp = wid >> 2;           // warpgroup: d-slice [0,32) or [32,64)
    const int wt = tid & 127;

    // affine A-fragment offsets (per-thread constants)
    const int row0 = warp_m * 32 + (lane & 7) + ((lane >> 3) & 1) * 8;
    const int row1 = row0 + 16;
    const int ahalf = lane >> 4;
    const uint32_t aw0 = (uint32_t)(row0 * 32 + ((ahalf ^ ((row0 >> 2) & 1)) << 4));
    const uint32_t aw1 = (uint32_t)(row1 * 32 + ((ahalf ^ ((row1 >> 2) & 1)) << 4));
    // B-fragment indices
    const int tl = lane >> 3;
    const int b_crem = (tl & 1) * 8 + (lane & 7);
    const int b_drem = (tl >> 1) * 8;

    char* xs0 = smem + SM_X + grp * 8192;
    char* xs1 = smem + SM_X + 16384 + grp * 8192;
    const uint32_t xb0 = sb + SM_X + grp * 8192;
    const uint32_t xb1 = xb0 + 16384;

    // ---- stage all three W ONCE via identity cp.async ----
#pragma unroll
    for (int i = 0; i < 24; i++) {
        const uint32_t dst = sb + (uint32_t)(tid * 16 + i * 4096);
        const char* src = g_wh + tid * 16 + i * 4096;
        asm volatile("cp.async.cg.shared.global [%0], [%1], 16;" :: "r"(dst), "l"(src));
    }
    asm volatile("cp.async.commit_group;" ::: "memory");
    asm volatile("cp.async.wait_group 0;" ::: "memory");
    __syncthreads();

    // hoisted per-thread constants
    const int r0 = warp_m * 32 + (lane >> 2);
    const float bq0 = bq[r0], bq1 = bq[r0 + 8], bq2 = bq[r0 + 16], bq3 = bq[r0 + 24];
    const float bvr[4] = {bv[r0], bv[r0 + 8], bv[r0 + 16], bv[r0 + 24]};

    // ---- persistent tile loop ----
    for (int t = blockIdx.x; t < N_TILES; t += GRID_X) {
        const int b = t >> 8;
        const int dt = (t & 255) * D_TILE + grp * 32;

        // stage this group's q slice into buf0
        {
            float4 pf[8];
            pf_load(pf, q + (long)b * Cn * Dn + dt, (long)Dn, wt);
            pf_store(xs0, pf, wt);
        }
        grp_bar(grp);

        float qp[2][4][4];
        proj1(sb + SM_WQ, xb0, aw0, aw1, b_crem, b_drem, qp);
#pragma unroll
        for (int n = 0; n < 4; n++) {
            qp[0][n][0] += bq0; qp[0][n][1] += bq0; qp[0][n][2] += bq1; qp[0][n][3] += bq1;
            qp[1][n][0] += bq2; qp[1][n][1] += bq2; qp[1][n][2] += bq3; qp[1][n][3] += bq3;
        }

        float acc[2][4][4], den[2][4][2];
#pragma unroll
        for (int tt = 0; tt < 2; tt++)
#pragma unroll
            for (int n = 0; n < 4; n++) {
                acc[tt][n][0] = acc[tt][n][1] = acc[tt][n][2] = acc[tt][n][3] = 0.0f;
                den[tt][n][0] = den[tt][n][1] = 0.0f;
            }

        grp_bar(grp);   // group's Q-proj readers done with buf0
        {
            float4 pf[8];
            pf_load(pf, kv + (long)(b * Cn) * Sn * Dn + dt, (long)Sn * Dn, wt);
            pf_store(xs0, pf, wt);
        }
        grp_bar(grp);

        float4 pf[8];
        for (int s = 0; s < Sn; s++) {
            const uint32_t xb = (s & 1) ? xb1 : xb0;
            char* nxt = ((s + 1) & 1) ? xs1 : xs0;

            if (s + 1 < Sn)
                pf_load(pf, kv + ((long)(b * Cn) * Sn + (s + 1)) * Dn + dt, (long)Sn * Dn, wt);

            float kp[2][4][4], vp[2][4][4];
            proj2(sb + SM_WK, sb + SM_WV, xb, aw0, aw1, b_crem, b_drem, kp, vp);

#pragma unroll
            for (int tt = 0; tt < 2; tt++)
#pragma unroll
                for (int n = 0; n < 4; n++) {
                    float pe = qp[tt][n][0] * kp[tt][n][0] + qp[tt][n][2] * kp[tt][n][2];
                    float po = qp[tt][n][1] * kp[tt][n][1] + qp[tt][n][3] * kp[tt][n][3];
                    pe += __shfl_xor_sync(0xffffffffu, pe, 4);
                    pe += __shfl_xor_sync(0xffffffffu, pe, 8);
                    pe += __shfl_xor_sync(0xffffffffu, pe, 16);
                    po += __shfl_xor_sync(0xffffffffu, po, 4);
                    po += __shfl_xor_sync(0xffffffffu, po, 8);
                    po += __shfl_xor_sync(0xffffffffu, po, 16);
                    const float we = __expf(ATT_SCALE * pe);
                    const float wo = __expf(ATT_SCALE * po);
                    den[tt][n][0] += we; den[tt][n][1] += wo;
                    acc[tt][n][0] = fmaf(we, vp[tt][n][0], acc[tt][n][0]);
                    acc[tt][n][1] = fmaf(wo, vp[tt][n][1], acc[tt][n][1]);
                    acc[tt][n][2] = fmaf(we, vp[tt][n][2], acc[tt][n][2]);
                    acc[tt][n][3] = fmaf(wo, vp[tt][n][3], acc[tt][n][3]);
                }

            if (s + 1 < Sn) pf_store(nxt, pf, wt);
            grp_bar(grp);
        }

        // output: out = acc/den + bv
#pragma unroll
        for (int tt = 0; tt < 2; tt++)
#pragma unroll
            for (int n = 0; n < 4; n++) {
                const int row = warp_m * 32 + tt * 16 + (lane >> 2);
                float* dst = out + ((long)(b * Cn + row)) * Dn + dt + n * 8 + (lane & 3) * 2;
                const float de = den[tt][n][0], dz = den[tt][n][1];
                float2 v0 = make_float2(acc[tt][n][0] / de + bvr[tt * 2],
                                        acc[tt][n][1] / dz + bvr[tt * 2]);
                float2 v1 = make_float2(acc[tt][n][2] / de + bvr[tt * 2 + 1],
                                        acc[tt][n][3] / dz + bvr[tt * 2 + 1]);
                *reinterpret_cast<float2*>(dst) = v0;
                *reinterpret_cast<float2*>(dst + (long)8 * Dn) = v1;
            }
    }
}

extern "C" void kernel_launch(void* const* d_in, const int* in_sizes, int n_in,
                              void* d_out, int out_size) {
    const float* q  = (const float*)d_in[0];
    const float* kv = (const float*)d_in[1];
    const float* Wq = (const float*)d_in[2];
    const float* bq = (const float*)d_in[3];
    const float* Wk = (const float*)d_in[4];
    // d_in[5] = bk: unused (softmax-invariant)
    const float* Wv = (const float*)d_in[6];
    const float* bv = (const float*)d_in[7];
    float* out = (float*)d_out;

    prep_w<<<48, 256>>>(Wq, Wk, Wv);

    cudaFuncSetAttribute(deform_attn_hmma,
                         cudaFuncAttributeMaxDynamicSharedMemorySize, SM_TOTAL);
    deform_attn_hmma<<<dim3(GRID_X, 1), NT, SM_TOTAL>>>(q, kv, bq, bv, out);
}

// round 15
// speedup vs baseline: 1.4094x; 1.0194x over previous
#include <cuda_runtime.h>
#include <cuda_fp16.h>
#include <cstdint>
#include <math.h>

// DeformAttn via ldmatrix + mma.sync (m16n8k16 fp16, fp32 accum) — base sm_103 ISA.
// Round 15 (= R14 with compile fix): R13 champion (persistent CTAs, ks-major affine W,
// group barriers) +
//  (a) prefetch STS moved to right after proj2 (drain covered by softmax block;
//      safe with double buffering: nxt's readers finished before last barrier)
//  (b) staging stores packed to 8-byte uint2 (16 -> 8 STS per thread per sample)

namespace {
constexpr int Bn = 4, Cn = 128, Sn = 9, Dn = 16384;
constexpr int D_TILE = 64;
constexpr int NT = 256;
constexpr int N_TILES = (Dn / D_TILE) * Bn;   // 1024
constexpr int GRID_X = 152;
constexpr float ATT_SCALE = 0.25f;

constexpr int SM_WQ = 0;            // 3 x 32KB ks-major fp16 W
constexpr int SM_WK = 32768;
constexpr int SM_WV = 65536;
constexpr int SM_X  = 98304;        // [buf 0/1][group 0/1] 8KB slices = 32KB
constexpr int SM_TOTAL = 131072;
}

__device__ __align__(16) char g_wh[3 * 32768];

__device__ __forceinline__ uint32_t smem_u32(const void* p) {
    uint32_t a;
    asm("{ .reg .u64 t; cvta.to.shared.u64 t, %1; cvt.u32.u64 %0, t; }" : "=r"(a) : "l"(p));
    return a;
}
__device__ __forceinline__ uint32_t h2_bits(__half2 h) {
    return *reinterpret_cast<uint32_t*>(&h);
}
// x slice rows: 64B (32 halfwords), 16B chunks XOR-swizzled by (row>>1)&3 (ks-affine)
__device__ __forceinline__ uint32_t swzX(int row, int colh) {
    int chunk = ((colh >> 3) & 3) ^ ((row >> 1) & 3);
    return (uint32_t)(row * 64 + chunk * 16 + (colh & 7) * 2);
}
__device__ __forceinline__ void ldsm4(uint32_t r[4], uint32_t addr) {
    asm volatile("ldmatrix.sync.aligned.m8n8.x4.shared.b16 {%0,%1,%2,%3}, [%4];"
                 : "=r"(r[0]), "=r"(r[1]), "=r"(r[2]), "=r"(r[3]) : "r"(addr));
}
__device__ __forceinline__ void ldsm4t(uint32_t r[4], uint32_t addr) {
    asm volatile("ldmatrix.sync.aligned.m8n8.x4.trans.shared.b16 {%0,%1,%2,%3}, [%4];"
                 : "=r"(r[0]), "=r"(r[1]), "=r"(r[2]), "=r"(r[3]) : "r"(addr));
}
__device__ __forceinline__ void mma16816(float d[4], const uint32_t a[4], const uint32_t b[2]) {
    asm volatile(
        "mma.sync.aligned.m16n8k16.row.col.f32.f16.f16.f32 "
        "{%0,%1,%2,%3},{%4,%5,%6,%7},{%8,%9},{%0,%1,%2,%3};"
        : "+f"(d[0]), "+f"(d[1]), "+f"(d[2]), "+f"(d[3])
        : "r"(a[0]), "r"(a[1]), "r"(a[2]), "r"(a[3]), "r"(b[0]), "r"(b[1]));
}
__device__ __forceinline__ void grp_bar(int g) {
    asm volatile("bar.sync %0, 128;" :: "r"(g + 1) : "memory");
}

// ---- prep kernel: W fp32 [o][c] -> ks-major conflict-free fp16 scratch ----
__global__ void prep_w(const float* __restrict__ Wq, const float* __restrict__ Wk,
                       const float* __restrict__ Wv) {
    const int t = blockIdx.x * 256 + threadIdx.x;   // 0..12287
    const int w = t >> 12;
    const int rem = t & 4095;
    const int o = rem >> 5, f4 = rem & 31;
    const float* W = (w == 0) ? Wq : (w == 1) ? Wk : Wv;
    const float4 v = *reinterpret_cast<const float4*>(W + o * 128 + f4 * 4);
    const int ks = f4 >> 2;
    const int half = (f4 >> 1) & 1;
    const int pos = (f4 & 1) * 4;
    char* dst = g_wh + w * 32768 + ks * 4096 + o * 32
              + ((half ^ ((o >> 2) & 1)) << 4) + pos * 2;
    *reinterpret_cast<__half2*>(dst)     = __floats2half2_rn(v.x, v.y);
    *reinterpret_cast<__half2*>(dst + 4) = __floats2half2_rn(v.z, v.w);
}

// ---- per-group x slice staging: 128 threads stage [128c x 32d] fp32 -> fp16 ----
__device__ __forceinline__ void pf_load(float4 pf[8], const float* __restrict__ src,
                                        long cstride, int wt) {
#pragma unroll
    for (int i = 0; i < 8; i++) {
        const int g = i * 128 + wt;
        const int c = g >> 3, d4 = (g & 7) * 4;
        pf[i] = *reinterpret_cast<const float4*>(src + (long)c * cstride + d4);
    }
}
// packed 8-byte stores: two half2 per element are contiguous and 8-aligned
__device__ __forceinline__ void pf_store(char* xb, const float4 pf[8], int wt) {
#pragma unroll
    for (int i = 0; i < 8; i++) {
        const int g = i * 128 + wt;
        const int c = g >> 3, d4 = (g & 7) * 4;
        const uint32_t off = swzX(c, d4);
        uint2 pk;
        pk.x = h2_bits(__floats2half2_rn(pf[i].x, pf[i].y));
        pk.y = h2_bits(__floats2half2_rn(pf[i].z, pf[i].w));
        *reinterpret_cast<uint2*>(xb + off) = pk;
    }
}

// fused K+V projection, warp tile m32 x n32, affine A addresses
__device__ __forceinline__ void proj2(uint32_t wbK, uint32_t wbV, uint32_t xb,
                                      uint32_t aw0, uint32_t aw1,
                                      int b_crem, int b_drem,
                                      float kp[2][4][4], float vp[2][4][4]) {
#pragma unroll
    for (int t = 0; t < 2; t++)
#pragma unroll
        for (int n = 0; n < 4; n++)
#pragma unroll
            for (int i = 0; i < 4; i++) { kp[t][n][i] = 0.0f; vp[t][n][i] = 0.0f; }
#pragma unroll
    for (int ks = 0; ks < 8; ks++) {
        uint32_t ak[2][4], av[2][4];
        ldsm4(ak[0], wbK + ks * 4096 + aw0);
        ldsm4(ak[1], wbK + ks * 4096 + aw1);
        ldsm4(av[0], wbV + ks * 4096 + aw0);
        ldsm4(av[1], wbV + ks * 4096 + aw1);
        const int c = ks * 16 + b_crem;
        uint32_t bf[4][2];
#pragma unroll
        for (int np = 0; np < 2; np++) {
            uint32_t r4[4];
            ldsm4t(r4, xb + swzX(c, np * 16 + b_drem));
            bf[np * 2][0] = r4[0]; bf[np * 2][1] = r4[1];
            bf[np * 2 + 1][0] = r4[2]; bf[np * 2 + 1][1] = r4[3];
        }
#pragma unroll
        for (int t = 0; t < 2; t++)
#pragma unroll
            for (int n = 0; n < 4; n++) {
                mma16816(kp[t][n], ak[t], bf[n]);
                mma16816(vp[t][n], av[t], bf[n]);
            }
    }
}
// single projection (Q only), affine A addresses
__device__ __forceinline__ void proj1(uint32_t wb, uint32_t xb,
                                      uint32_t aw0, uint32_t aw1,
                                      int b_crem, int b_drem, float acc[2][4][4]) {
#pragma unroll
    for (int t = 0; t < 2; t++)
#pragma unroll
        for (int n = 0; n < 4; n++)
#pragma unroll
            for (int i = 0; i < 4; i++) acc[t][n][i] = 0.0f;
#pragma unroll
    for (int ks = 0; ks < 8; ks++) {
        uint32_t a[2][4];
        ldsm4(a[0], wb + ks * 4096 + aw0);
        ldsm4(a[1], wb + ks * 4096 + aw1);
        const int c = ks * 16 + b_crem;
        uint32_t bf[4][2];
#pragma unroll
        for (int np = 0; np < 2; np++) {
            uint32_t r4[4];
            ldsm4t(r4, xb + swzX(c, np * 16 + b_drem));
            bf[np * 2][0] = r4[0]; bf[np * 2][1] = r4[1];
            bf[np * 2 + 1][0] = r4[2]; bf[np * 2 + 1][1] = r4[3];
        }
#pragma unroll
        for (int t = 0; t < 2; t++)
#pragma unroll
            for (int n = 0; n < 4; n++) mma16816(acc[t][n], a[t], bf[n]);
    }
}

__global__ void __launch_bounds__(NT, 1)
deform_attn_hmma(const float* __restrict__ q,  const float* __restrict__ kv,
                 const float* __restrict__ bq, const float* __restrict__ bv,
                 float* __restrict__ out)
{
    extern __shared__ char smem[];
    const uint32_t sb = smem_u32(smem);
    const int tid = threadIdx.x, lane = tid & 31, wid = tid >> 5;
    const int warp_m = wid & 3;
    const int grp = wid >> 2;           // warpgroup: d-slice [0,32) or [32,64)
    const int wt = tid & 127;

    // affine A-fragment offsets (per-thread constants)
    const int row0 = warp_m * 32 + (lane & 7) + ((lane >> 3) & 1) * 8;
    const int row1 = row0 + 16;
    const int ahalf = lane >> 4;
    const uint32_t aw0 = (uint32_t)(row0 * 32 + ((ahalf ^ ((row0 >> 2) & 1)) << 4));
    const uint32_t aw1 = (uint32_t)(row1 * 32 + ((ahalf ^ ((row1 >> 2) & 1)) << 4));
    // B-fragment indices
    const int tl = lane >> 3;
    const int b_crem = (tl & 1) * 8 + (lane & 7);
    const int b_drem = (tl >> 1) * 8;

    char* xs0 = smem + SM_X + grp * 8192;
    char* xs1 = smem + SM_X + 16384 + grp * 8192;
    const uint32_t xb0 = sb + SM_X + grp * 8192;
    const uint32_t xb1 = xb0 + 16384;

    // ---- stage all three W ONCE via identity cp.async ----
#pragma unroll
    for (int i = 0; i < 24; i++) {
        const uint32_t dst = sb + (uint32_t)(tid * 16 + i * 4096);
        const char* src = g_wh + tid * 16 + i * 4096;
        asm volatile("cp.async.cg.shared.global [%0], [%1], 16;" :: "r"(dst), "l"(src));
    }
    asm volatile("cp.async.commit_group;" ::: "memory");
    asm volatile("cp.async.wait_group 0;" ::: "memory");
    __syncthreads();

    const int r0 = warp_m * 32 + (lane >> 2);
    const float bq0 = bq[r0], bq1 = bq[r0 + 8], bq2 = bq[r0 + 16], bq3 = bq[r0 + 24];
    const float bvr[4] = {bv[r0], bv[r0 + 8], bv[r0 + 16], bv[r0 + 24]};

    // ---- persistent tile loop ----
    for (int t = blockIdx.x; t < N_TILES; t += GRID_X) {
        const int b = t >> 8;
        const int dt = (t & 255) * D_TILE + grp * 32;

        {
            float4 pf[8];
            pf_load(pf, q + (long)b * Cn * Dn + dt, (long)Dn, wt);
            pf_store(xs0, pf, wt);
        }
        grp_bar(grp);

        float qp[2][4][4];
        proj1(sb + SM_WQ, xb0, aw0, aw1, b_crem, b_drem, qp);
#pragma unroll
        for (int n = 0; n < 4; n++) {
            qp[0][n][0] += bq0; qp[0][n][1] += bq0; qp[0][n][2] += bq1; qp[0][n][3] += bq1;
            qp[1][n][0] += bq2; qp[1][n][1] += bq2; qp[1][n][2] += bq3; qp[1][n][3] += bq3;
        }

        float acc[2][4][4], den[2][4][2];
#pragma unroll
        for (int tt = 0; tt < 2; tt++)
#pragma unroll
            for (int n = 0; n < 4; n++) {
                acc[tt][n][0] = acc[tt][n][1] = acc[tt][n][2] = acc[tt][n][3] = 0.0f;
                den[tt][n][0] = den[tt][n][1] = 0.0f;
            }

        grp_bar(grp);   // group's Q-proj readers done with buf0
        {
            float4 pf[8];
            pf_load(pf, kv + (long)(b * Cn) * Sn * Dn + dt, (long)Sn * Dn, wt);
            pf_store(xs0, pf, wt);
        }
        grp_bar(grp);

        float4 pf[8];
        for (int s = 0; s < Sn; s++) {
            const uint32_t xb = (s & 1) ? xb1 : xb0;
            char* nxt = ((s + 1) & 1) ? xs1 : xs0;

            if (s + 1 < Sn)
                pf_load(pf, kv + ((long)(b * Cn) * Sn + (s + 1)) * Dn + dt, (long)Sn * Dn, wt);

            float kp[2][4][4], vp[2][4][4];
            proj2(sb + SM_WK, sb + SM_WV, xb, aw0, aw1, b_crem, b_drem, kp, vp);

            // store prefetch NOW: nxt's previous readers (sample s-1) finished before
            // the last barrier; STS drain is covered by the softmax block below.
            if (s + 1 < Sn) pf_store(nxt, pf, wt);

#pragma unroll
            for (int tt = 0; tt < 2; tt++)
#pragma unroll
                for (int n = 0; n < 4; n++) {
                    float pe = qp[tt][n][0] * kp[tt][n][0] + qp[tt][n][2] * kp[tt][n][2];
                    float po = qp[tt][n][1] * kp[tt][n][1] + qp[tt][n][3] * kp[tt][n][3];
                    pe += __shfl_xor_sync(0xffffffffu, pe, 4);
                    pe += __shfl_xor_sync(0xffffffffu, pe, 8);
                    pe += __shfl_xor_sync(0xffffffffu, pe, 16);
                    po += __shfl_xor_sync(0xffffffffu, po, 4);
                    po += __shfl_xor_sync(0xffffffffu, po, 8);
                    po += __shfl_xor_sync(0xffffffffu, po, 16);
                    const float we = __expf(ATT_SCALE * pe);
                    const float wo = __expf(ATT_SCALE * po);
                    den[tt][n][0] += we; den[tt][n][1] += wo;
                    acc[tt][n][0] = fmaf(we, vp[tt][n][0], acc[tt][n][0]);
                    acc[tt][n][1] = fmaf(wo, vp[tt][n][1], acc[tt][n][1]);
                    acc[tt][n][2] = fmaf(we, vp[tt][n][2], acc[tt][n][2]);
                    acc[tt][n][3] = fmaf(wo, vp[tt][n][3], acc[tt][n][3]);
                }

            grp_bar(grp);
        }

        // output: out = acc/den + bv
#pragma unroll
        for (int tt = 0; tt < 2; tt++)
#pragma unroll
            for (int n = 0; n < 4; n++) {
                const int row = warp_m * 32 + tt * 16 + (lane >> 2);
                float* dst = out + ((long)(b * Cn + row)) * Dn + dt + n * 8 + (lane & 3) * 2;
                const float de = den[tt][n][0], dz = den[tt][n][1];
                float2 v0 = make_float2(acc[tt][n][0] / de + bvr[tt * 2],
                                        acc[tt][n][1] / dz + bvr[tt * 2]);
                float2 v1 = make_float2(acc[tt][n][2] / de + bvr[tt * 2 + 1],
                                        acc[tt][n][3] / dz + bvr[tt * 2 + 1]);
                *reinterpret_cast<float2*>(dst) = v0;
                *reinterpret_cast<float2*>(dst + (long)8 * Dn) = v1;
            }
    }
}

extern "C" void kernel_launch(void* const* d_in, const int* in_sizes, int n_in,
                              void* d_out, int out_size) {
    const float* q  = (const float*)d_in[0];
    const float* kv = (const float*)d_in[1];
    const float* Wq = (const float*)d_in[2];
    const float* bq = (const float*)d_in[3];
    const float* Wk = (const float*)d_in[4];
    // d_in[5] = bk: unused (softmax-invariant)
    const float* Wv = (const float*)d_in[6];
    const float* bv = (const float*)d_in[7];
    float* out = (float*)d_out;

    prep_w<<<48, 256>>>(Wq, Wk, Wv);

    cudaFuncSetAttribute(deform_attn_hmma,
                         cudaFuncAttributeMaxDynamicSharedMemorySize, SM_TOTAL);
    deform_attn_hmma<<<dim3(GRID_X, 1), NT, SM_TOTAL>>>(q, kv, bq, bv, out);
}

// round 16
// speedup vs baseline: 1.4169x; 1.0053x over previous
#include <cuda_runtime.h>
#include <cuda_fp16.h>
#include <cstdint>
#include <math.h>

// DeformAttn via ldmatrix + mma.sync (m16n8k16 fp16, fp32 accum) — base sm_103 ISA.
// Round 16: R15 champion + pipelined tile transitions:
//  (a) kv sample-0 LDG issued BEFORE proj1 (covered by Q-proj MMAs), stored to xs1;
//      sample-loop parity flipped (s even -> xs1).
//  (b) next tile's q staged in the s=8 slot (LDG under proj2, STS under softmax,
//      target xs0 = nxt at s=8) -> tile transition needs no extra barrier.
//  Barriers per tile: 12 -> 10.

namespace {
constexpr int Bn = 4, Cn = 128, Sn = 9, Dn = 16384;
constexpr int D_TILE = 64;
constexpr int NT = 256;
constexpr int N_TILES = (Dn / D_TILE) * Bn;   // 1024
constexpr int GRID_X = 152;
constexpr float ATT_SCALE = 0.25f;

constexpr int SM_WQ = 0;            // 3 x 32KB ks-major fp16 W
constexpr int SM_WK = 32768;
constexpr int SM_WV = 65536;
constexpr int SM_X  = 98304;        // [buf 0/1][group 0/1] 8KB slices = 32KB
constexpr int SM_TOTAL = 131072;
}

__device__ __align__(16) char g_wh[3 * 32768];

__device__ __forceinline__ uint32_t smem_u32(const void* p) {
    uint32_t a;
    asm("{ .reg .u64 t; cvta.to.shared.u64 t, %1; cvt.u32.u64 %0, t; }" : "=r"(a) : "l"(p));
    return a;
}
__device__ __forceinline__ uint32_t h2_bits(__half2 h) {
    return *reinterpret_cast<uint32_t*>(&h);
}
// x slice rows: 64B (32 halfwords), 16B chunks XOR-swizzled by (row>>1)&3 (ks-affine)
__device__ __forceinline__ uint32_t swzX(int row, int colh) {
    int chunk = ((colh >> 3) & 3) ^ ((row >> 1) & 3);
    return (uint32_t)(row * 64 + chunk * 16 + (colh & 7) * 2);
}
__device__ __forceinline__ void ldsm4(uint32_t r[4], uint32_t addr) {
    asm volatile("ldmatrix.sync.aligned.m8n8.x4.shared.b16 {%0,%1,%2,%3}, [%4];"
                 : "=r"(r[0]), "=r"(r[1]), "=r"(r[2]), "=r"(r[3]) : "r"(addr));
}
__device__ __forceinline__ void ldsm4t(uint32_t r[4], uint32_t addr) {
    asm volatile("ldmatrix.sync.aligned.m8n8.x4.trans.shared.b16 {%0,%1,%2,%3}, [%4];"
                 : "=r"(r[0]), "=r"(r[1]), "=r"(r[2]), "=r"(r[3]) : "r"(addr));
}
__device__ __forceinline__ void mma16816(float d[4], const uint32_t a[4], const uint32_t b[2]) {
    asm volatile(
        "mma.sync.aligned.m16n8k16.row.col.f32.f16.f16.f32 "
        "{%0,%1,%2,%3},{%4,%5,%6,%7},{%8,%9},{%0,%1,%2,%3};"
        : "+f"(d[0]), "+f"(d[1]), "+f"(d[2]), "+f"(d[3])
        : "r"(a[0]), "r"(a[1]), "r"(a[2]), "r"(a[3]), "r"(b[0]), "r"(b[1]));
}
__device__ __forceinline__ void grp_bar(int g) {
    asm volatile("bar.sync %0, 128;" :: "r"(g + 1) : "memory");
}

// ---- prep kernel: W fp32 [o][c] -> ks-major conflict-free fp16 scratch ----
__global__ void prep_w(const float* __restrict__ Wq, const float* __restrict__ Wk,
                       const float* __restrict__ Wv) {
    const int t = blockIdx.x * 256 + threadIdx.x;   // 0..12287
    const int w = t >> 12;
    const int rem = t & 4095;
    const int o = rem >> 5, f4 = rem & 31;
    const float* W = (w == 0) ? Wq : (w == 1) ? Wk : Wv;
    const float4 v = *reinterpret_cast<const float4*>(W + o * 128 + f4 * 4);
    const int ks = f4 >> 2;
    const int half = (f4 >> 1) & 1;
    const int pos = (f4 & 1) * 4;
    char* dst = g_wh + w * 32768 + ks * 4096 + o * 32
              + ((half ^ ((o >> 2) & 1)) << 4) + pos * 2;
    *reinterpret_cast<__half2*>(dst)     = __floats2half2_rn(v.x, v.y);
    *reinterpret_cast<__half2*>(dst + 4) = __floats2half2_rn(v.z, v.w);
}

// ---- per-group x slice staging: 128 threads stage [128c x 32d] fp32 -> fp16 ----
__device__ __forceinline__ void pf_load(float4 pf[8], const float* __restrict__ src,
                                        long cstride, int wt) {
#pragma unroll
    for (int i = 0; i < 8; i++) {
        const int g = i * 128 + wt;
        const int c = g >> 3, d4 = (g & 7) * 4;
        pf[i] = *reinterpret_cast<const float4*>(src + (long)c * cstride + d4);
    }
}
__device__ __forceinline__ void pf_store(char* xb, const float4 pf[8], int wt) {
#pragma unroll
    for (int i = 0; i < 8; i++) {
        const int g = i * 128 + wt;
        const int c = g >> 3, d4 = (g & 7) * 4;
        const uint32_t off = swzX(c, d4);
        uint2 pk;
        pk.x = h2_bits(__floats2half2_rn(pf[i].x, pf[i].y));
        pk.y = h2_bits(__floats2half2_rn(pf[i].z, pf[i].w));
        *reinterpret_cast<uint2*>(xb + off) = pk;
    }
}

// fused K+V projection, warp tile m32 x n32, affine A addresses
__device__ __forceinline__ void proj2(uint32_t wbK, uint32_t wbV, uint32_t xb,
                                      uint32_t aw0, uint32_t aw1,
                                      int b_crem, int b_drem,
                                      float kp[2][4][4], float vp[2][4][4]) {
#pragma unroll
    for (int t = 0; t < 2; t++)
#pragma unroll
        for (int n = 0; n < 4; n++)
#pragma unroll
            for (int i = 0; i < 4; i++) { kp[t][n][i] = 0.0f; vp[t][n][i] = 0.0f; }
#pragma unroll
    for (int ks = 0; ks < 8; ks++) {
        uint32_t ak[2][4], av[2][4];
        ldsm4(ak[0], wbK + ks * 4096 + aw0);
        ldsm4(ak[1], wbK + ks * 4096 + aw1);
        ldsm4(av[0], wbV + ks * 4096 + aw0);
        ldsm4(av[1], wbV + ks * 4096 + aw1);
        const int c = ks * 16 + b_crem;
        uint32_t bf[4][2];
#pragma unroll
        for (int np = 0; np < 2; np++) {
            uint32_t r4[4];
            ldsm4t(r4, xb + swzX(c, np * 16 + b_drem));
            bf[np * 2][0] = r4[0]; bf[np * 2][1] = r4[1];
            bf[np * 2 + 1][0] = r4[2]; bf[np * 2 + 1][1] = r4[3];
        }
#pragma unroll
        for (int t = 0; t < 2; t++)
#pragma unroll
            for (int n = 0; n < 4; n++) {
                mma16816(kp[t][n], ak[t], bf[n]);
                mma16816(vp[t][n], av[t], bf[n]);
            }
    }
}
// single projection (Q only), affine A addresses
__device__ __forceinline__ void proj1(uint32_t wb, uint32_t xb,
                                      uint32_t aw0, uint32_t aw1,
                                      int b_crem, int b_drem, float acc[2][4][4]) {
#pragma unroll
    for (int t = 0; t < 2; t++)
#pragma unroll
        for (int n = 0; n < 4; n++)
#pragma unroll
            for (int i = 0; i < 4; i++) acc[t][n][i] = 0.0f;
#pragma unroll
    for (int ks = 0; ks < 8; ks++) {
        uint32_t a[2][4];
        ldsm4(a[0], wb + ks * 4096 + aw0);
        ldsm4(a[1], wb + ks * 4096 + aw1);
        const int c = ks * 16 + b_crem;
        uint32_t bf[4][2];
#pragma unroll
        for (int np = 0; np < 2; np++) {
            uint32_t r4[4];
            ldsm4t(r4, xb + swzX(c, np * 16 + b_drem));
            bf[np * 2][0] = r4[0]; bf[np * 2][1] = r4[1];
            bf[np * 2 + 1][0] = r4[2]; bf[np * 2 + 1][1] = r4[3];
        }
#pragma unroll
        for (int t = 0; t < 2; t++)
#pragma unroll
            for (int n = 0; n < 4; n++) mma16816(acc[t][n], a[t], bf[n]);
    }
}

__global__ void __launch_bounds__(NT, 1)
deform_attn_hmma(const float* __restrict__ q,  const float* __restrict__ kv,
                 const float* __restrict__ bq, const float* __restrict__ bv,
                 float* __restrict__ out)
{
    extern __shared__ char smem[];
    const uint32_t sb = smem_u32(smem);
    const int tid = threadIdx.x, lane = tid & 31, wid = tid >> 5;
    const int warp_m = wid & 3;
    const int grp = wid >> 2;           // warpgroup: d-slice [0,32) or [32,64)
    const int wt = tid & 127;

    // affine A-fragment offsets (per-thread constants)
    const int row0 = warp_m * 32 + (lane & 7) + ((lane >> 3) & 1) * 8;
    const int row1 = row0 + 16;
    const int ahalf = lane >> 4;
    const uint32_t aw0 = (uint32_t)(row0 * 32 + ((ahalf ^ ((row0 >> 2) & 1)) << 4));
    const uint32_t aw1 = (uint32_t)(row1 * 32 + ((ahalf ^ ((row1 >> 2) & 1)) << 4));
    // B-fragment indices
    const int tl = lane >> 3;
    const int b_crem = (tl & 1) * 8 + (lane & 7);
    const int b_drem = (tl >> 1) * 8;

    char* xs0 = smem + SM_X + grp * 8192;
    char* xs1 = smem + SM_X + 16384 + grp * 8192;
    const uint32_t xb0 = sb + SM_X + grp * 8192;
    const uint32_t xb1 = xb0 + 16384;

    // ---- stage all three W ONCE via identity cp.async ----
#pragma unroll
    for (int i = 0; i < 24; i++) {
        const uint32_t dst = sb + (uint32_t)(tid * 16 + i * 4096);
        const char* src = g_wh + tid * 16 + i * 4096;
        asm volatile("cp.async.cg.shared.global [%0], [%1], 16;" :: "r"(dst), "l"(src));
    }
    asm volatile("cp.async.commit_group;" ::: "memory");
    asm volatile("cp.async.wait_group 0;" ::: "memory");
    __syncthreads();

    const int r0 = warp_m * 32 + (lane >> 2);
    const float bq0 = bq[r0], bq1 = bq[r0 + 8], bq2 = bq[r0 + 16], bq3 = bq[r0 + 24];
    const float bvr[4] = {bv[r0], bv[r0 + 8], bv[r0 + 16], bv[r0 + 24]};

    // ---- prologue: stage first tile's q slice into xs0 ----
    {
        const int t0 = blockIdx.x;
        const int b0 = t0 >> 8;
        const int dt0 = (t0 & 255) * D_TILE + grp * 32;
        float4 pf[8];
        pf_load(pf, q + (long)b0 * Cn * Dn + dt0, (long)Dn, wt);
        pf_store(xs0, pf, wt);
    }
    grp_bar(grp);

    // ---- persistent tile loop ----
    for (int t = blockIdx.x; t < N_TILES; t += GRID_X) {
        const int b = t >> 8;
        const int dt = (t & 255) * D_TILE + grp * 32;
        const int tn = t + GRID_X;
        const long kvbase = (long)(b * Cn) * Sn * Dn + dt;

        // kv sample-0 LDG issued now; latency covered by proj1 below
        float4 pf[8];
        pf_load(pf, kv + kvbase, (long)Sn * Dn, wt);

        // Q projection (reads xs0 = q tile)
        float qp[2][4][4];
        proj1(sb + SM_WQ, xb0, aw0, aw1, b_crem, b_drem, qp);
#pragma unroll
        for (int n = 0; n < 4; n++) {
            qp[0][n][0] += bq0; qp[0][n][1] += bq0; qp[0][n][2] += bq1; qp[0][n][3] += bq1;
            qp[1][n][0] += bq2; qp[1][n][1] += bq2; qp[1][n][2] += bq3; qp[1][n][3] += bq3;
        }

        float acc[2][4][4], den[2][4][2];
#pragma unroll
        for (int tt = 0; tt < 2; tt++)
#pragma unroll
            for (int n = 0; n < 4; n++) {
                acc[tt][n][0] = acc[tt][n][1] = acc[tt][n][2] = acc[tt][n][3] = 0.0f;
                den[tt][n][0] = den[tt][n][1] = 0.0f;
            }

        pf_store(xs1, pf, wt);   // kv0 -> xs1 (no conflict with proj1's xs0 reads)
        grp_bar(grp);

        // sample loop, flipped parity: s even -> xs1, s odd -> xs0
        for (int s = 0; s < Sn; s++) {
            const uint32_t xb = (s & 1) ? xb0 : xb1;
            char* nxt = (s & 1) ? xs1 : xs0;   // at s=8: xs0 (= q target)

            if (s + 1 < Sn) {
                pf_load(pf, kv + kvbase + (long)(s + 1) * Dn, (long)Sn * Dn, wt);
            } else if (tn < N_TILES) {
                // s=8 slot: prefetch NEXT tile's q (LDG under proj2, STS under softmax)
                const int bn = tn >> 8;
                const int dtn = (tn & 255) * D_TILE + grp * 32;
                pf_load(pf, q + (long)bn * Cn * Dn + dtn, (long)Dn, wt);
            }

            float kp[2][4][4], vp[2][4][4];
            proj2(sb + SM_WK, sb + SM_WV, xb, aw0, aw1, b_crem, b_drem, kp, vp);

            // store prefetch: nxt's previous readers finished before the last barrier
            if (s + 1 < Sn || tn < N_TILES) pf_store(nxt, pf, wt);

#pragma unroll
            for (int tt = 0; tt < 2; tt++)
#pragma unroll
                for (int n = 0; n < 4; n++) {
                    float pe = qp[tt][n][0] * kp[tt][n][0] + qp[tt][n][2] * kp[tt][n][2];
                    float po = qp[tt][n][1] * kp[tt][n][1] + qp[tt][n][3] * kp[tt][n][3];
                    pe += __shfl_xor_sync(0xffffffffu, pe, 4);
                    pe += __shfl_xor_sync(0xffffffffu, pe, 8);
                    pe += __shfl_xor_sync(0xffffffffu, pe, 16);
                    po += __shfl_xor_sync(0xffffffffu, po, 4);
                    po += __shfl_xor_sync(0xffffffffu, po, 8);
                    po += __shfl_xor_sync(0xffffffffu, po, 16);
                    const float we = __expf(ATT_SCALE * pe);
                    const float wo = __expf(ATT_SCALE * po);
                    den[tt][n][0] += we; den[tt][n][1] += wo;
                    acc[tt][n][0] = fmaf(we, vp[tt][n][0], acc[tt][n][0]);
                    acc[tt][n][1] = fmaf(wo, vp[tt][n][1], acc[tt][n][1]);
                    acc[tt][n][2] = fmaf(we, vp[tt][n][2], acc[tt][n][2]);
                    acc[tt][n][3] = fmaf(wo, vp[tt][n][3], acc[tt][n][3]);
                }

            grp_bar(grp);
        }

        // epilogue: out = acc/den + bv  (no smem; next tile's proj1 is already safe)
#pragma unroll
        for (int tt = 0; tt < 2; tt++)
#pragma unroll
            for (int n = 0; n < 4; n++) {
                const int row = warp_m * 32 + tt * 16 + (lane >> 2);
                float* dst = out + ((long)(b * Cn + row)) * Dn + dt + n * 8 + (lane & 3) * 2;
                const float de = den[tt][n][0], dz = den[tt][n][1];
                float2 v0 = make_float2(acc[tt][n][0] / de + bvr[tt * 2],
                                        acc[tt][n][1] / dz + bvr[tt * 2]);
                float2 v1 = make_float2(acc[tt][n][2] / de + bvr[tt * 2 + 1],
                                        acc[tt][n][3] / dz + bvr[tt * 2 + 1]);
                *reinterpret_cast<float2*>(dst) = v0;
                *reinterpret_cast<float2*>(dst + (long)8 * Dn) = v1;
            }
    }
}

extern "C" void kernel_launch(void* const* d_in, const int* in_sizes, int n_in,
                              void* d_out, int out_size) {
    const float* q  = (const float*)d_in[0];
    const float* kv = (const float*)d_in[1];
    const float* Wq = (const float*)d_in[2];
    const float* bq = (const float*)d_in[3];
    const float* Wk = (const float*)d_in[4];
    // d_in[5] = bk: unused (softmax-invariant)
    const float* Wv = (const float*)d_in[6];
    const float* bv = (const float*)d_in[7];
    float* out = (float*)d_out;

    prep_w<<<48, 256>>>(Wq, Wk, Wv);

    cudaFuncSetAttribute(deform_attn_hmma,
                         cudaFuncAttributeMaxDynamicSharedMemorySize, SM_TOTAL);
    deform_attn_hmma<<<dim3(GRID_X, 1), NT, SM_TOTAL>>>(q, kv, bq, bv, out);
}